// round 15
// baseline (speedup 1.0000x reference)
#include <cuda_runtime.h>
#include <math.h>
#include <stdint.h>

#define N_TOK 1024
#define DIMV  512
#define HEADS 8
#define DH    64
#define JTOT  1026
#define JPAD  1088          // 17 * 64 = 34 * 32
#define INV_EPS 10.0f
#define EPSF    0.1f
#define LOGK    2.0794415416798357f   // log(8)
#define CD_ITERS 50

// ---------------- scratch ----------------
__device__ float g_xn[N_TOK * DIMV];
__device__ float g_q [HEADS * N_TOK * DH];
__device__ float g_k [HEADS * JPAD * DH];
__device__ float g_v [HEADS * JPAD * DH];
__device__ float g_s [HEADS * N_TOK * JPAD];
__device__ float g_o [N_TOK * DIMV];
__device__ float g_o2[N_TOK * DIMV];
__device__ float g_o3[N_TOK * DIMV];
__device__ float g_o4[N_TOK * DIMV];

// ---------------- packed f32x2 helpers ----------------
__device__ __forceinline__ void ffma2(uint64_t& acc, uint64_t a, uint64_t b) {
    asm("fma.rn.f32x2 %0, %1, %2, %0;" : "+l"(acc) : "l"(a), "l"(b));
}
__device__ __forceinline__ uint64_t bcast2(float v) {
    uint64_t r;
    const uint32_t u = __float_as_uint(v);
    asm("mov.b64 %0, {%1, %1};" : "=l"(r) : "r"(u));
    return r;
}
__device__ __forceinline__ float lo32(uint64_t v) { return __uint_as_float((uint32_t)v); }
__device__ __forceinline__ float hi32(uint64_t v) { return __uint_as_float((uint32_t)(v >> 32)); }

// ---------------- block reduction ----------------
__device__ __forceinline__ float block_sum_256(float v, float* red) {
#pragma unroll
    for (int o = 16; o; o >>= 1) v += __shfl_xor_sync(0xffffffffu, v, o);
    __syncthreads();
    if ((threadIdx.x & 31) == 0) red[threadIdx.x >> 5] = v;
    __syncthreads();
    v = red[threadIdx.x & 7];
#pragma unroll
    for (int o = 4; o; o >>= 1) v += __shfl_xor_sync(0xffffffffu, v, o);
    return v;
}

// ---------------- fused LayerNorm + null-kv/pad fill ----------------
__global__ void ln_fill_kernel(const float* __restrict__ x, const float* __restrict__ gam,
                               const float* __restrict__ bet,
                               const float* __restrict__ null_kv) {
    if (blockIdx.x >= 1024) {
        const int idx = (blockIdx.x - 1024) * 256 + threadIdx.x;
        const int h = idx >> 12;
        const int r = (idx >> 6) & 63;
        const int d = idx & 63;
        if (r < 2) {
            g_k[(h * JPAD + r) * DH + d] = null_kv[((0 * HEADS + h) * 2 + r) * DH + d];
            g_v[(h * JPAD + r) * DH + d] = null_kv[((1 * HEADS + h) * 2 + r) * DH + d];
        } else {
            const int j = 1024 + r;
            g_k[(h * JPAD + j) * DH + d] = 0.0f;
            g_v[(h * JPAD + j) * DH + d] = 0.0f;
        }
        return;
    }
    __shared__ float red[8];
    const int row = blockIdx.x;
    const int tid = threadIdx.x;
    const float v0 = x[row * DIMV + tid];
    const float v1 = x[row * DIMV + tid + 256];
    float s  = v0 + v1;
    float sq = v0 * v0 + v1 * v1;
    s  = block_sum_256(s,  red);
    sq = block_sum_256(sq, red);
    const float mean = s * (1.0f / 512.0f);
    const float var  = sq * (1.0f / 512.0f) - mean * mean;
    const float rstd = rsqrtf(var + 1e-5f);
    g_xn[row * DIMV + tid]       = (v0 - mean) * rstd * gam[tid]       + bet[tid];
    g_xn[row * DIMV + tid + 256] = (v1 - mean) * rstd * gam[tid + 256] + bet[tid + 256];
}

// ---------------- QKV GEMM: 64x64 tiles, f32x2 + reg prefetch ----------------
__global__ void gemm_qkv(const float* __restrict__ B) {
    __shared__ __align__(16) float As[16][64];
    __shared__ __align__(16) float Bs[16][64];
    const float* __restrict__ A = g_xn;
    const int bx = blockIdx.x, by = blockIdx.y, tid = threadIdx.x;
    const int tx = tid & 15, ty = tid >> 4;
    const int ar = tid >> 2, ac = (tid & 3) << 2;
    const int br = tid >> 4, bc = (tid & 15) << 2;
    uint64_t acc2[2][4] = {};

    float4 a4 = *(const float4*)(A + (by * 64 + ar) * 512 + ac);
    float4 b4 = *(const float4*)(B + (size_t)br * 1536 + bx * 64 + bc);

    for (int k0 = 0; k0 < 512; k0 += 16) {
        As[ac + 0][ar] = a4.x; As[ac + 1][ar] = a4.y;
        As[ac + 2][ar] = a4.z; As[ac + 3][ar] = a4.w;
        *(float4*)&Bs[br][bc] = b4;
        __syncthreads();
        if (k0 + 16 < 512) {
            a4 = *(const float4*)(A + (by * 64 + ar) * 512 + k0 + 16 + ac);
            b4 = *(const float4*)(B + (size_t)(k0 + 16 + br) * 1536 + bx * 64 + bc);
        }
#pragma unroll
        for (int kk = 0; kk < 16; kk++) {
            const uint64_t* ap = (const uint64_t*)&As[kk][ty << 2];
            uint64_t ra[2];
            ra[0] = ap[0]; ra[1] = ap[1];
            float4 bq = *(const float4*)&Bs[kk][tx << 2];
            uint64_t rb[4];
            rb[0] = bcast2(bq.x); rb[1] = bcast2(bq.y);
            rb[2] = bcast2(bq.z); rb[3] = bcast2(bq.w);
#pragma unroll
            for (int p = 0; p < 2; p++)
#pragma unroll
                for (int j = 0; j < 4; j++)
                    ffma2(acc2[p][j], ra[p], rb[j]);
        }
        __syncthreads();
    }
#pragma unroll
    for (int p = 0; p < 2; p++) {
#pragma unroll
        for (int j = 0; j < 4; j++) {
            const int col = bx * 64 + (tx << 2) + j;
            const int h = (col >> 6) & 7, d = col & 63, w = col >> 9;
            const int row0 = by * 64 + (ty << 2) + 2 * p;
            const float vlo = lo32(acc2[p][j]);
            const float vhi = hi32(acc2[p][j]);
            if (w == 0) {
                g_q[(h * N_TOK + row0) * DH + d]     = vlo * 0.125f;
                g_q[(h * N_TOK + row0 + 1) * DH + d] = vhi * 0.125f;
            } else if (w == 1) {
                g_k[(h * JPAD + row0 + 2) * DH + d] = vlo;
                g_k[(h * JPAD + row0 + 3) * DH + d] = vhi;
            } else {
                g_v[(h * JPAD + row0 + 2) * DH + d] = vlo;
                g_v[(h * JPAD + row0 + 3) * DH + d] = vhi;
            }
        }
    }
}

// ---------------- out projection GEMM: sums 4 av partials ----------------
__global__ void gemm_proj(const float* __restrict__ B, float* __restrict__ C) {
    __shared__ __align__(16) float As[16][64];
    __shared__ __align__(16) float Bs[16][64];
    const int bx = blockIdx.x, by = blockIdx.y, tid = threadIdx.x;
    const int tx = tid & 15, ty = tid >> 4;
    const int ar = tid >> 2, ac = (tid & 3) << 2;
    const int br = tid >> 4, bc = (tid & 15) << 2;
    uint64_t acc2[2][4] = {};

    const int aoff0 = (by * 64 + ar) * 512 + ac;
    float4 a4  = *(const float4*)(g_o + aoff0);
    float4 a4b = *(const float4*)(g_o2 + aoff0);
    float4 a4c = *(const float4*)(g_o3 + aoff0);
    float4 a4d = *(const float4*)(g_o4 + aoff0);
    a4.x = (a4.x + a4b.x) + (a4c.x + a4d.x);
    a4.y = (a4.y + a4b.y) + (a4c.y + a4d.y);
    a4.z = (a4.z + a4b.z) + (a4c.z + a4d.z);
    a4.w = (a4.w + a4b.w) + (a4c.w + a4d.w);
    float4 b4 = *(const float4*)(B + (size_t)br * 512 + bx * 64 + bc);

    for (int k0 = 0; k0 < 512; k0 += 16) {
        As[ac + 0][ar] = a4.x; As[ac + 1][ar] = a4.y;
        As[ac + 2][ar] = a4.z; As[ac + 3][ar] = a4.w;
        *(float4*)&Bs[br][bc] = b4;
        __syncthreads();
        if (k0 + 16 < 512) {
            const int aoff = (by * 64 + ar) * 512 + k0 + 16 + ac;
            a4  = *(const float4*)(g_o + aoff);
            a4b = *(const float4*)(g_o2 + aoff);
            a4c = *(const float4*)(g_o3 + aoff);
            a4d = *(const float4*)(g_o4 + aoff);
            a4.x = (a4.x + a4b.x) + (a4c.x + a4d.x);
            a4.y = (a4.y + a4b.y) + (a4c.y + a4d.y);
            a4.z = (a4.z + a4b.z) + (a4c.z + a4d.z);
            a4.w = (a4.w + a4b.w) + (a4c.w + a4d.w);
            b4 = *(const float4*)(B + (size_t)(k0 + 16 + br) * 512 + bx * 64 + bc);
        }
#pragma unroll
        for (int kk = 0; kk < 16; kk++) {
            const uint64_t* ap = (const uint64_t*)&As[kk][ty << 2];
            uint64_t ra[2];
            ra[0] = ap[0]; ra[1] = ap[1];
            float4 bq = *(const float4*)&Bs[kk][tx << 2];
            uint64_t rb[4];
            rb[0] = bcast2(bq.x); rb[1] = bcast2(bq.y);
            rb[2] = bcast2(bq.z); rb[3] = bcast2(bq.w);
#pragma unroll
            for (int p = 0; p < 2; p++)
#pragma unroll
                for (int j = 0; j < 4; j++)
                    ffma2(acc2[p][j], ra[p], rb[j]);
        }
        __syncthreads();
    }
#pragma unroll
    for (int p = 0; p < 2; p++) {
        const int row0 = by * 64 + (ty << 2) + 2 * p;
        const int colb = bx * 64 + (tx << 2);
        C[row0 * 512 + colb + 0] = lo32(acc2[p][0]);
        C[row0 * 512 + colb + 1] = lo32(acc2[p][1]);
        C[row0 * 512 + colb + 2] = lo32(acc2[p][2]);
        C[row0 * 512 + colb + 3] = lo32(acc2[p][3]);
        C[(row0 + 1) * 512 + colb + 0] = hi32(acc2[p][0]);
        C[(row0 + 1) * 512 + colb + 1] = hi32(acc2[p][1]);
        C[(row0 + 1) * 512 + colb + 2] = hi32(acc2[p][2]);
        C[(row0 + 1) * 512 + colb + 3] = hi32(acc2[p][3]);
    }
}

// ---------------- sim = q . k^T: 128(i) x 64(j) tiles, f32x2, occ 3 -------------------
__global__ void __launch_bounds__(256, 3) sim_kernel() {
    const int f = blockIdx.x;
    const int h = blockIdx.y;
    int it2 = __float2int_rd(sqrtf((float)(f + 1))) - 1;
    while ((it2 + 1) * (it2 + 3) <= f) it2++;
    while (it2 * (it2 + 2) > f) it2--;
    const int jt = f - it2 * (it2 + 2);

    __shared__ __align__(16) float Qs[32][132];
    __shared__ __align__(16) float Ks[32][68];
    const int tid = threadIdx.x;
    const int tx = tid & 15, ty = tid >> 4;
    uint64_t acc2[4][4] = {};

#pragma unroll
    for (int dc = 0; dc < 64; dc += 32) {
        {
            const int row = tid >> 1;
            const int base = ((h << 10) + it2 * 128 + row) * DH + dc + ((tid & 1) << 4);
#pragma unroll
            for (int t = 0; t < 4; t++) {
                float4 q4 = *(const float4*)&g_q[base + t * 4];
                const int off = ((tid & 1) << 4) + t * 4;
                Qs[off + 0][row] = q4.x; Qs[off + 1][row] = q4.y;
                Qs[off + 2][row] = q4.z; Qs[off + 3][row] = q4.w;
            }
        }
        {
            const int row = tid >> 2;
            const int base = (h * JPAD + jt * 64 + row) * DH + dc + ((tid & 3) << 3);
#pragma unroll
            for (int t = 0; t < 2; t++) {
                float4 k4 = *(const float4*)&g_k[base + t * 4];
                const int off = ((tid & 3) << 3) + t * 4;
                Ks[off + 0][row] = k4.x; Ks[off + 1][row] = k4.y;
                Ks[off + 2][row] = k4.z; Ks[off + 3][row] = k4.w;
            }
        }
        __syncthreads();
#pragma unroll 8
        for (int d = 0; d < 32; d++) {
            const uint64_t* ap = (const uint64_t*)&Qs[d][ty << 3];
            uint64_t ra[4];
            ra[0] = ap[0]; ra[1] = ap[1]; ra[2] = ap[2]; ra[3] = ap[3];
            float4 kq = *(const float4*)&Ks[d][tx << 2];
            uint64_t rb[4];
            rb[0] = bcast2(kq.x); rb[1] = bcast2(kq.y);
            rb[2] = bcast2(kq.z); rb[3] = bcast2(kq.w);
#pragma unroll
            for (int p = 0; p < 4; p++)
#pragma unroll
                for (int j = 0; j < 4; j++)
                    ffma2(acc2[p][j], ra[p], rb[j]);
        }
        __syncthreads();
    }
#pragma unroll
    for (int p = 0; p < 4; p++) {
        const int i0 = it2 * 128 + (ty << 3) + 2 * p;
        float* sr0 = g_s + (size_t)(h * N_TOK + i0) * JPAD + jt * 64 + (tx << 2);
        float* sr1 = sr0 + JPAD;
        *(float4*)sr0 = make_float4(lo32(acc2[p][0]), lo32(acc2[p][1]),
                                    lo32(acc2[p][2]), lo32(acc2[p][3]));
        *(float4*)sr1 = make_float4(hi32(acc2[p][0]), hi32(acc2[p][1]),
                                    hi32(acc2[p][2]), hi32(acc2[p][3]));
    }
}

// ---------------- coordinate descent: bucketed kernels, forward row order -------------
template<int MAXU>
__device__ __forceinline__ void cd_row(float* __restrict__ srow, int lane, int jmax,
                                       int nchunk, int chunks) {
    float E1[MAXU];
    float tm = -3.4e38f;
#pragma unroll
    for (int u = 0; u < MAXU; u++) {
        E1[u] = -3.4e38f;
        if (u < nchunk) {
            const int j = lane + u * 32;
            if (j < jmax) { E1[u] = srow[j]; tm = fmaxf(tm, E1[u]); }
        }
    }
#pragma unroll
    for (int o = 16; o; o >>= 1) tm = fmaxf(tm, __shfl_xor_sync(0xffffffffu, tm, o));
    const float m = tm;
#pragma unroll
    for (int u = 0; u < MAXU; u++)
        if (u < nchunk)
            E1[u] = (E1[u] > -3.0e38f) ? __expf((E1[u] - m) * INV_EPS) : 0.0f;

    float a = EPSF * (LOGK - __logf((float)jmax));

    for (int it = 1; it < CD_ITERS; it++) {
        const float w = __expf((a + m) * INV_EPS);
        float ls0 = 0.0f, ls1 = 0.0f;
#pragma unroll
        for (int u = 0; u < MAXU; u++) {
            if (u < nchunk) {
                const float e = E1[u];
                const float c = fminf(e, w * (e * e));
                if (u & 1) ls1 += c; else ls0 += c;
            }
        }
        float ls = ls0 + ls1;
#pragma unroll
        for (int o = 16; o; o >>= 1) ls += __shfl_xor_sync(0xffffffffu, ls, o);
        const float a_new = EPSF * LOGK - m - EPSF * __logf(ls);
        const float da = fabsf(a_new - a);
        a = a_new;
        if (da < 5e-7f) break;
    }

    const float w = __expf((a + m) * INV_EPS);
#pragma unroll
    for (int u = 0; u < MAXU + 3; u++) {
        if (u < chunks) {
            const int j = lane + u * 32;
            float val = 0.0f;
            if (u < MAXU && u < nchunk) {
                const float eu = w * E1[u];
                val = fminf(eu, eu * eu);
            }
            srow[j] = val;
        }
    }
}

template<int MAXU>
__global__ void cd_bucket(int ibase) {
    const int wg   = (blockIdx.x * blockDim.x + threadIdx.x) >> 5;
    const int lane = threadIdx.x & 31;
    const int i = ibase + (wg >> 3);
    const int h = wg & 7;
    const int jmax = i + 3;
    const int nchunk = (jmax + 31) >> 5;
    const int chunks = ((i >> 6) + 2) << 1;
    float* srow = g_s + (size_t)(h * N_TOK + i) * JPAD;
    cd_row<MAXU>(srow, lane, jmax, nchunk, chunks);
}

// ---------------- out = attn . v : split-K 4 over 32-j chunks, f32x2 ------------------
__global__ void av_kernel() {
    const int it = blockIdx.x;
    const int h  = blockIdx.y;
    const int sp = blockIdx.z;                 // 0..3
    const int C = 2 * (it + 2);                // total 32-j chunks
    const int c0 = (C * sp) >> 2;
    const int c1 = (C * (sp + 1)) >> 2;

    __shared__ __align__(16) float Ps[32][66];
    __shared__ __align__(16) float Vs[32][68];
    const int tid = threadIdx.x;
    const int tx = tid & 15, ty = tid >> 4;
    const int pi = tid >> 2, pj = (tid & 3) << 3;
    const int vj = tid >> 3, vd = (tid & 7) << 3;
    uint64_t acc2[2][4] = {};

    for (int jc = c0; jc < c1; jc++) {
        const float* pg = g_s + (size_t)(h * N_TOK + it * 64 + pi) * JPAD + jc * 32 + pj;
        float4 p0 = *(const float4*)pg;
        float4 p1 = *(const float4*)(pg + 4);
        Ps[pj + 0][pi] = p0.x; Ps[pj + 1][pi] = p0.y;
        Ps[pj + 2][pi] = p0.z; Ps[pj + 3][pi] = p0.w;
        Ps[pj + 4][pi] = p1.x; Ps[pj + 5][pi] = p1.y;
        Ps[pj + 6][pi] = p1.z; Ps[pj + 7][pi] = p1.w;
        const float* vg = g_v + (h * JPAD + jc * 32 + vj) * DH + vd;
        *(float4*)&Vs[vj][vd]     = *(const float4*)vg;
        *(float4*)&Vs[vj][vd + 4] = *(const float4*)(vg + 4);
        __syncthreads();
#pragma unroll 8
        for (int j = 0; j < 32; j++) {
            const uint64_t* ap = (const uint64_t*)&Ps[j][ty << 2];
            uint64_t ra[2];
            ra[0] = ap[0]; ra[1] = ap[1];
            float4 vq = *(const float4*)&Vs[j][tx << 2];
            uint64_t rb[4];
            rb[0] = bcast2(vq.x); rb[1] = bcast2(vq.y);
            rb[2] = bcast2(vq.z); rb[3] = bcast2(vq.w);
#pragma unroll
            for (int p = 0; p < 2; p++)
#pragma unroll
                for (int jj = 0; jj < 4; jj++)
                    ffma2(acc2[p][jj], ra[p], rb[jj]);
        }
        __syncthreads();
    }
    float* outp = (sp == 0) ? g_o : (sp == 1) ? g_o2 : (sp == 2) ? g_o3 : g_o4;
#pragma unroll
    for (int p = 0; p < 2; p++) {
        const int row0 = it * 64 + (ty << 2) + 2 * p;
        float* o0 = outp + row0 * DIMV + h * DH + (tx << 2);
        float* o1 = o0 + DIMV;
        *(float4*)o0 = make_float4(lo32(acc2[p][0]), lo32(acc2[p][1]),
                                   lo32(acc2[p][2]), lo32(acc2[p][3]));
        *(float4*)o1 = make_float4(hi32(acc2[p][0]), hi32(acc2[p][1]),
                                   hi32(acc2[p][2]), hi32(acc2[p][3]));
    }
}

// ---------------- launch ----------------
extern "C" void kernel_launch(void* const* d_in, const int* in_sizes, int n_in,
                              void* d_out, int out_size) {
    const float* x       = (const float*)d_in[0];
    const float* w_qkv   = (const float*)d_in[1];
    const float* w_out   = (const float*)d_in[2];
    const float* null_kv = (const float*)d_in[3];
    const float* ln_g    = (const float*)d_in[4];
    const float* ln_b    = (const float*)d_in[5];
    float* out = (float*)d_out;

    ln_fill_kernel<<<1152, 256>>>(x, ln_g, ln_b, null_kv);
    gemm_qkv   <<<dim3(24, 16), 256>>>(w_qkv);
    sim_kernel <<<dim3(80, HEADS), 256>>>();
    cd_bucket<8 ><<<508, 128>>>(0);     // rows    0..253
    cd_bucket<16><<<512, 128>>>(254);   // rows  254..509
    cd_bucket<24><<<512, 128>>>(510);   // rows  510..765
    cd_bucket<33><<<516, 128>>>(766);   // rows  766..1023
    av_kernel  <<<dim3(16, HEADS, 4), 256>>>();
    gemm_proj  <<<dim3(8, 16), 256>>>(w_out, out);
}

// round 16
// speedup vs baseline: 1.1597x; 1.1597x over previous
#include <cuda_runtime.h>
#include <math.h>
#include <stdint.h>

#define N_TOK 1024
#define DIMV  512
#define HEADS 8
#define DH    64
#define JTOT  1026
#define JPAD  1088          // 17 * 64 = 34 * 32
#define INV_EPS 10.0f
#define EPSF    0.1f
#define LOGK    2.0794415416798357f   // log(8)
#define CD_ITERS 50

// ---------------- scratch ----------------
__device__ float g_xn[N_TOK * DIMV];
__device__ float g_q [HEADS * N_TOK * DH];
__device__ float g_k [HEADS * JPAD * DH];
__device__ float g_v [HEADS * JPAD * DH];
__device__ float g_s [HEADS * N_TOK * JPAD];
__device__ float g_o [N_TOK * DIMV];
__device__ float g_o2[N_TOK * DIMV];
__device__ float g_o3[N_TOK * DIMV];
__device__ float g_o4[N_TOK * DIMV];

// ---------------- packed f32x2 helpers ----------------
__device__ __forceinline__ void ffma2(uint64_t& acc, uint64_t a, uint64_t b) {
    asm("fma.rn.f32x2 %0, %1, %2, %0;" : "+l"(acc) : "l"(a), "l"(b));
}
__device__ __forceinline__ uint64_t bcast2(float v) {
    uint64_t r;
    const uint32_t u = __float_as_uint(v);
    asm("mov.b64 %0, {%1, %1};" : "=l"(r) : "r"(u));
    return r;
}
__device__ __forceinline__ float lo32(uint64_t v) { return __uint_as_float((uint32_t)v); }
__device__ __forceinline__ float hi32(uint64_t v) { return __uint_as_float((uint32_t)(v >> 32)); }

// ---------------- block reduction ----------------
__device__ __forceinline__ float block_sum_256(float v, float* red) {
#pragma unroll
    for (int o = 16; o; o >>= 1) v += __shfl_xor_sync(0xffffffffu, v, o);
    __syncthreads();
    if ((threadIdx.x & 31) == 0) red[threadIdx.x >> 5] = v;
    __syncthreads();
    v = red[threadIdx.x & 7];
#pragma unroll
    for (int o = 4; o; o >>= 1) v += __shfl_xor_sync(0xffffffffu, v, o);
    return v;
}

// ---------------- fused LayerNorm + null-kv/pad fill ----------------
__global__ void ln_fill_kernel(const float* __restrict__ x, const float* __restrict__ gam,
                               const float* __restrict__ bet,
                               const float* __restrict__ null_kv) {
    if (blockIdx.x >= 1024) {
        const int idx = (blockIdx.x - 1024) * 256 + threadIdx.x;
        const int h = idx >> 12;
        const int r = (idx >> 6) & 63;
        const int d = idx & 63;
        if (r < 2) {
            g_k[(h * JPAD + r) * DH + d] = null_kv[((0 * HEADS + h) * 2 + r) * DH + d];
            g_v[(h * JPAD + r) * DH + d] = null_kv[((1 * HEADS + h) * 2 + r) * DH + d];
        } else {
            const int j = 1024 + r;
            g_k[(h * JPAD + j) * DH + d] = 0.0f;
            g_v[(h * JPAD + j) * DH + d] = 0.0f;
        }
        return;
    }
    __shared__ float red[8];
    const int row = blockIdx.x;
    const int tid = threadIdx.x;
    const float v0 = x[row * DIMV + tid];
    const float v1 = x[row * DIMV + tid + 256];
    float s  = v0 + v1;
    float sq = v0 * v0 + v1 * v1;
    s  = block_sum_256(s,  red);
    sq = block_sum_256(sq, red);
    const float mean = s * (1.0f / 512.0f);
    const float var  = sq * (1.0f / 512.0f) - mean * mean;
    const float rstd = rsqrtf(var + 1e-5f);
    g_xn[row * DIMV + tid]       = (v0 - mean) * rstd * gam[tid]       + bet[tid];
    g_xn[row * DIMV + tid + 256] = (v1 - mean) * rstd * gam[tid + 256] + bet[tid + 256];
}

// ---------------- QKV GEMM: 64x64 tiles, f32x2 + reg prefetch (R12) -------------------
__global__ void gemm_qkv(const float* __restrict__ B) {
    __shared__ __align__(16) float As[16][64];
    __shared__ __align__(16) float Bs[16][64];
    const float* __restrict__ A = g_xn;
    const int bx = blockIdx.x, by = blockIdx.y, tid = threadIdx.x;
    const int tx = tid & 15, ty = tid >> 4;
    const int ar = tid >> 2, ac = (tid & 3) << 2;
    const int br = tid >> 4, bc = (tid & 15) << 2;
    uint64_t acc2[2][4] = {};

    float4 a4 = *(const float4*)(A + (by * 64 + ar) * 512 + ac);
    float4 b4 = *(const float4*)(B + (size_t)br * 1536 + bx * 64 + bc);

    for (int k0 = 0; k0 < 512; k0 += 16) {
        As[ac + 0][ar] = a4.x; As[ac + 1][ar] = a4.y;
        As[ac + 2][ar] = a4.z; As[ac + 3][ar] = a4.w;
        *(float4*)&Bs[br][bc] = b4;
        __syncthreads();
        if (k0 + 16 < 512) {
            a4 = *(const float4*)(A + (by * 64 + ar) * 512 + k0 + 16 + ac);
            b4 = *(const float4*)(B + (size_t)(k0 + 16 + br) * 1536 + bx * 64 + bc);
        }
#pragma unroll
        for (int kk = 0; kk < 16; kk++) {
            const uint64_t* ap = (const uint64_t*)&As[kk][ty << 2];
            uint64_t ra[2];
            ra[0] = ap[0]; ra[1] = ap[1];
            float4 bq = *(const float4*)&Bs[kk][tx << 2];
            uint64_t rb[4];
            rb[0] = bcast2(bq.x); rb[1] = bcast2(bq.y);
            rb[2] = bcast2(bq.z); rb[3] = bcast2(bq.w);
#pragma unroll
            for (int p = 0; p < 2; p++)
#pragma unroll
                for (int j = 0; j < 4; j++)
                    ffma2(acc2[p][j], ra[p], rb[j]);
        }
        __syncthreads();
    }
#pragma unroll
    for (int p = 0; p < 2; p++) {
#pragma unroll
        for (int j = 0; j < 4; j++) {
            const int col = bx * 64 + (tx << 2) + j;
            const int h = (col >> 6) & 7, d = col & 63, w = col >> 9;
            const int row0 = by * 64 + (ty << 2) + 2 * p;
            const float vlo = lo32(acc2[p][j]);
            const float vhi = hi32(acc2[p][j]);
            if (w == 0) {
                g_q[(h * N_TOK + row0) * DH + d]     = vlo * 0.125f;
                g_q[(h * N_TOK + row0 + 1) * DH + d] = vhi * 0.125f;
            } else if (w == 1) {
                g_k[(h * JPAD + row0 + 2) * DH + d] = vlo;
                g_k[(h * JPAD + row0 + 3) * DH + d] = vhi;
            } else {
                g_v[(h * JPAD + row0 + 2) * DH + d] = vlo;
                g_v[(h * JPAD + row0 + 3) * DH + d] = vhi;
            }
        }
    }
}

// ---------------- out projection GEMM: sums 4 av partials (R14) ----------------
__global__ void gemm_proj(const float* __restrict__ B, float* __restrict__ C) {
    __shared__ __align__(16) float As[16][64];
    __shared__ __align__(16) float Bs[16][64];
    const int bx = blockIdx.x, by = blockIdx.y, tid = threadIdx.x;
    const int tx = tid & 15, ty = tid >> 4;
    const int ar = tid >> 2, ac = (tid & 3) << 2;
    const int br = tid >> 4, bc = (tid & 15) << 2;
    uint64_t acc2[2][4] = {};

    const int aoff0 = (by * 64 + ar) * 512 + ac;
    float4 a4  = *(const float4*)(g_o + aoff0);
    float4 a4b = *(const float4*)(g_o2 + aoff0);
    float4 a4c = *(const float4*)(g_o3 + aoff0);
    float4 a4d = *(const float4*)(g_o4 + aoff0);
    a4.x = (a4.x + a4b.x) + (a4c.x + a4d.x);
    a4.y = (a4.y + a4b.y) + (a4c.y + a4d.y);
    a4.z = (a4.z + a4b.z) + (a4c.z + a4d.z);
    a4.w = (a4.w + a4b.w) + (a4c.w + a4d.w);
    float4 b4 = *(const float4*)(B + (size_t)br * 512 + bx * 64 + bc);

    for (int k0 = 0; k0 < 512; k0 += 16) {
        As[ac + 0][ar] = a4.x; As[ac + 1][ar] = a4.y;
        As[ac + 2][ar] = a4.z; As[ac + 3][ar] = a4.w;
        *(float4*)&Bs[br][bc] = b4;
        __syncthreads();
        if (k0 + 16 < 512) {
            const int aoff = (by * 64 + ar) * 512 + k0 + 16 + ac;
            a4  = *(const float4*)(g_o + aoff);
            a4b = *(const float4*)(g_o2 + aoff);
            a4c = *(const float4*)(g_o3 + aoff);
            a4d = *(const float4*)(g_o4 + aoff);
            a4.x = (a4.x + a4b.x) + (a4c.x + a4d.x);
            a4.y = (a4.y + a4b.y) + (a4c.y + a4d.y);
            a4.z = (a4.z + a4b.z) + (a4c.z + a4d.z);
            a4.w = (a4.w + a4b.w) + (a4c.w + a4d.w);
            b4 = *(const float4*)(B + (size_t)(k0 + 16 + br) * 512 + bx * 64 + bc);
        }
#pragma unroll
        for (int kk = 0; kk < 16; kk++) {
            const uint64_t* ap = (const uint64_t*)&As[kk][ty << 2];
            uint64_t ra[2];
            ra[0] = ap[0]; ra[1] = ap[1];
            float4 bq = *(const float4*)&Bs[kk][tx << 2];
            uint64_t rb[4];
            rb[0] = bcast2(bq.x); rb[1] = bcast2(bq.y);
            rb[2] = bcast2(bq.z); rb[3] = bcast2(bq.w);
#pragma unroll
            for (int p = 0; p < 2; p++)
#pragma unroll
                for (int j = 0; j < 4; j++)
                    ffma2(acc2[p][j], ra[p], rb[j]);
        }
        __syncthreads();
    }
#pragma unroll
    for (int p = 0; p < 2; p++) {
        const int row0 = by * 64 + (ty << 2) + 2 * p;
        const int colb = bx * 64 + (tx << 2);
        C[row0 * 512 + colb + 0] = lo32(acc2[p][0]);
        C[row0 * 512 + colb + 1] = lo32(acc2[p][1]);
        C[row0 * 512 + colb + 2] = lo32(acc2[p][2]);
        C[row0 * 512 + colb + 3] = lo32(acc2[p][3]);
        C[(row0 + 1) * 512 + colb + 0] = hi32(acc2[p][0]);
        C[(row0 + 1) * 512 + colb + 1] = hi32(acc2[p][1]);
        C[(row0 + 1) * 512 + colb + 2] = hi32(acc2[p][2]);
        C[(row0 + 1) * 512 + colb + 3] = hi32(acc2[p][3]);
    }
}

// ---------------- sim = q . k^T: 128(i) x 64(j) tiles, f32x2, occ 3 (R14) -------------
__global__ void __launch_bounds__(256, 3) sim_kernel() {
    const int f = blockIdx.x;
    const int h = blockIdx.y;
    int it2 = __float2int_rd(sqrtf((float)(f + 1))) - 1;
    while ((it2 + 1) * (it2 + 3) <= f) it2++;
    while (it2 * (it2 + 2) > f) it2--;
    const int jt = f - it2 * (it2 + 2);

    __shared__ __align__(16) float Qs[32][132];
    __shared__ __align__(16) float Ks[32][68];
    const int tid = threadIdx.x;
    const int tx = tid & 15, ty = tid >> 4;
    uint64_t acc2[4][4] = {};

#pragma unroll
    for (int dc = 0; dc < 64; dc += 32) {
        {
            const int row = tid >> 1;
            const int base = ((h << 10) + it2 * 128 + row) * DH + dc + ((tid & 1) << 4);
#pragma unroll
            for (int t = 0; t < 4; t++) {
                float4 q4 = *(const float4*)&g_q[base + t * 4];
                const int off = ((tid & 1) << 4) + t * 4;
                Qs[off + 0][row] = q4.x; Qs[off + 1][row] = q4.y;
                Qs[off + 2][row] = q4.z; Qs[off + 3][row] = q4.w;
            }
        }
        {
            const int row = tid >> 2;
            const int base = (h * JPAD + jt * 64 + row) * DH + dc + ((tid & 3) << 3);
#pragma unroll
            for (int t = 0; t < 2; t++) {
                float4 k4 = *(const float4*)&g_k[base + t * 4];
                const int off = ((tid & 3) << 3) + t * 4;
                Ks[off + 0][row] = k4.x; Ks[off + 1][row] = k4.y;
                Ks[off + 2][row] = k4.z; Ks[off + 3][row] = k4.w;
            }
        }
        __syncthreads();
#pragma unroll 8
        for (int d = 0; d < 32; d++) {
            const uint64_t* ap = (const uint64_t*)&Qs[d][ty << 3];
            uint64_t ra[4];
            ra[0] = ap[0]; ra[1] = ap[1]; ra[2] = ap[2]; ra[3] = ap[3];
            float4 kq = *(const float4*)&Ks[d][tx << 2];
            uint64_t rb[4];
            rb[0] = bcast2(kq.x); rb[1] = bcast2(kq.y);
            rb[2] = bcast2(kq.z); rb[3] = bcast2(kq.w);
#pragma unroll
            for (int p = 0; p < 4; p++)
#pragma unroll
                for (int j = 0; j < 4; j++)
                    ffma2(acc2[p][j], ra[p], rb[j]);
        }
        __syncthreads();
    }
#pragma unroll
    for (int p = 0; p < 4; p++) {
        const int i0 = it2 * 128 + (ty << 3) + 2 * p;
        float* sr0 = g_s + (size_t)(h * N_TOK + i0) * JPAD + jt * 64 + (tx << 2);
        float* sr1 = sr0 + JPAD;
        *(float4*)sr0 = make_float4(lo32(acc2[p][0]), lo32(acc2[p][1]),
                                    lo32(acc2[p][2]), lo32(acc2[p][3]));
        *(float4*)sr1 = make_float4(hi32(acc2[p][0]), hi32(acc2[p][1]),
                                    hi32(acc2[p][2]), hi32(acc2[p][3]));
    }
}

// ---------------- coordinate descent: single fused kernel, forward order (R12) --------
template<int MAXU>
__device__ __forceinline__ void cd_row(float* __restrict__ srow, int lane, int jmax,
                                       int nchunk, int chunks) {
    float E1[MAXU];
    float tm = -3.4e38f;
#pragma unroll
    for (int u = 0; u < MAXU; u++) {
        E1[u] = -3.4e38f;
        if (u < nchunk) {
            const int j = lane + u * 32;
            if (j < jmax) { E1[u] = srow[j]; tm = fmaxf(tm, E1[u]); }
        }
    }
#pragma unroll
    for (int o = 16; o; o >>= 1) tm = fmaxf(tm, __shfl_xor_sync(0xffffffffu, tm, o));
    const float m = tm;
#pragma unroll
    for (int u = 0; u < MAXU; u++)
        if (u < nchunk)
            E1[u] = (E1[u] > -3.0e38f) ? __expf((E1[u] - m) * INV_EPS) : 0.0f;

    float a = EPSF * (LOGK - __logf((float)jmax));

    for (int it = 1; it < CD_ITERS; it++) {
        const float w = __expf((a + m) * INV_EPS);
        float ls0 = 0.0f, ls1 = 0.0f;
#pragma unroll
        for (int u = 0; u < MAXU; u++) {
            if (u < nchunk) {
                const float e = E1[u];
                const float c = fminf(e, w * (e * e));
                if (u & 1) ls1 += c; else ls0 += c;
            }
        }
        float ls = ls0 + ls1;
#pragma unroll
        for (int o = 16; o; o >>= 1) ls += __shfl_xor_sync(0xffffffffu, ls, o);
        const float a_new = EPSF * LOGK - m - EPSF * __logf(ls);
        const float da = fabsf(a_new - a);
        a = a_new;
        if (da < 5e-7f) break;
    }

    const float w = __expf((a + m) * INV_EPS);
#pragma unroll
    for (int u = 0; u < MAXU + 3; u++) {
        if (u < chunks) {
            const int j = lane + u * 32;
            float val = 0.0f;
            if (u < MAXU && u < nchunk) {
                const float eu = w * E1[u];
                val = fminf(eu, eu * eu);
            }
            srow[j] = val;
        }
    }
}

__global__ void cd_kernel() {
    const int wg   = (blockIdx.x * blockDim.x + threadIdx.x) >> 5;
    const int lane = threadIdx.x & 31;
    const int i = wg >> 3, h = wg & 7;
    const int jmax = i + 3;
    const int nchunk = (jmax + 31) >> 5;
    const int chunks = ((i >> 6) + 2) << 1;
    float* srow = g_s + (size_t)(h * N_TOK + i) * JPAD;
    if (i < 254)      cd_row<8 >(srow, lane, jmax, nchunk, chunks);
    else if (i < 510) cd_row<16>(srow, lane, jmax, nchunk, chunks);
    else if (i < 766) cd_row<24>(srow, lane, jmax, nchunk, chunks);
    else              cd_row<33>(srow, lane, jmax, nchunk, chunks);
}

// ---------------- out = attn . v : split-K 4 over 32-j chunks, f32x2 (R14) ------------
__global__ void av_kernel() {
    const int it = blockIdx.x;
    const int h  = blockIdx.y;
    const int sp = blockIdx.z;                 // 0..3
    const int C = 2 * (it + 2);                // total 32-j chunks
    const int c0 = (C * sp) >> 2;
    const int c1 = (C * (sp + 1)) >> 2;

    __shared__ __align__(16) float Ps[32][66];
    __shared__ __align__(16) float Vs[32][68];
    const int tid = threadIdx.x;
    const int tx = tid & 15, ty = tid >> 4;
    const int pi = tid >> 2, pj = (tid & 3) << 3;
    const int vj = tid >> 3, vd = (tid & 7) << 3;
    uint64_t acc2[2][4] = {};

    for (int jc = c0; jc < c1; jc++) {
        const float* pg = g_s + (size_t)(h * N_TOK + it * 64 + pi) * JPAD + jc * 32 + pj;
        float4 p0 = *(const float4*)pg;
        float4 p1 = *(const float4*)(pg + 4);
        Ps[pj + 0][pi] = p0.x; Ps[pj + 1][pi] = p0.y;
        Ps[pj + 2][pi] = p0.z; Ps[pj + 3][pi] = p0.w;
        Ps[pj + 4][pi] = p1.x; Ps[pj + 5][pi] = p1.y;
        Ps[pj + 6][pi] = p1.z; Ps[pj + 7][pi] = p1.w;
        const float* vg = g_v + (h * JPAD + jc * 32 + vj) * DH + vd;
        *(float4*)&Vs[vj][vd]     = *(const float4*)vg;
        *(float4*)&Vs[vj][vd + 4] = *(const float4*)(vg + 4);
        __syncthreads();
#pragma unroll 8
        for (int j = 0; j < 32; j++) {
            const uint64_t* ap = (const uint64_t*)&Ps[j][ty << 2];
            uint64_t ra[2];
            ra[0] = ap[0]; ra[1] = ap[1];
            float4 vq = *(const float4*)&Vs[j][tx << 2];
            uint64_t rb[4];
            rb[0] = bcast2(vq.x); rb[1] = bcast2(vq.y);
            rb[2] = bcast2(vq.z); rb[3] = bcast2(vq.w);
#pragma unroll
            for (int p = 0; p < 2; p++)
#pragma unroll
                for (int jj = 0; jj < 4; jj++)
                    ffma2(acc2[p][jj], ra[p], rb[jj]);
        }
        __syncthreads();
    }
    float* outp = (sp == 0) ? g_o : (sp == 1) ? g_o2 : (sp == 2) ? g_o3 : g_o4;
#pragma unroll
    for (int p = 0; p < 2; p++) {
        const int row0 = it * 64 + (ty << 2) + 2 * p;
        float* o0 = outp + row0 * DIMV + h * DH + (tx << 2);
        float* o1 = o0 + DIMV;
        *(float4*)o0 = make_float4(lo32(acc2[p][0]), lo32(acc2[p][1]),
                                   lo32(acc2[p][2]), lo32(acc2[p][3]));
        *(float4*)o1 = make_float4(hi32(acc2[p][0]), hi32(acc2[p][1]),
                                   hi32(acc2[p][2]), hi32(acc2[p][3]));
    }
}

// ---------------- launch ----------------
extern "C" void kernel_launch(void* const* d_in, const int* in_sizes, int n_in,
                              void* d_out, int out_size) {
    const float* x       = (const float*)d_in[0];
    const float* w_qkv   = (const float*)d_in[1];
    const float* w_out   = (const float*)d_in[2];
    const float* null_kv = (const float*)d_in[3];
    const float* ln_g    = (const float*)d_in[4];
    const float* ln_b    = (const float*)d_in[5];
    float* out = (float*)d_out;

    ln_fill_kernel<<<1152, 256>>>(x, ln_g, ln_b, null_kv);
    gemm_qkv   <<<dim3(24, 16), 256>>>(w_qkv);
    sim_kernel <<<dim3(80, HEADS), 256>>>();
    cd_kernel  <<<2048, 128>>>();
    av_kernel  <<<dim3(16, HEADS, 4), 256>>>();
    gemm_proj  <<<dim3(8, 16), 256>>>(w_out, out);
}

// round 17
// speedup vs baseline: 1.1764x; 1.0144x over previous
#include <cuda_runtime.h>
#include <math.h>
#include <stdint.h>

#define N_TOK 1024
#define DIMV  512
#define HEADS 8
#define DH    64
#define JTOT  1026
#define JPAD  1088          // 17 * 64 = 34 * 32
#define INV_EPS 10.0f
#define EPSF    0.1f
#define LOGK    2.0794415416798357f   // log(8)
#define CD_ITERS 50

// ---------------- scratch ----------------
__device__ float g_xn[N_TOK * DIMV];
__device__ float g_q [HEADS * N_TOK * DH];
__device__ float g_k [HEADS * JPAD * DH];
__device__ float g_v [HEADS * JPAD * DH];
__device__ float g_s [HEADS * N_TOK * JPAD];
__device__ float g_o [N_TOK * DIMV];
__device__ float g_o2[N_TOK * DIMV];
__device__ float g_o3[N_TOK * DIMV];
__device__ float g_o4[N_TOK * DIMV];

// ---------------- packed f32x2 helpers ----------------
__device__ __forceinline__ void ffma2(uint64_t& acc, uint64_t a, uint64_t b) {
    asm("fma.rn.f32x2 %0, %1, %2, %0;" : "+l"(acc) : "l"(a), "l"(b));
}
__device__ __forceinline__ uint64_t bcast2(float v) {
    uint64_t r;
    const uint32_t u = __float_as_uint(v);
    asm("mov.b64 %0, {%1, %1};" : "=l"(r) : "r"(u));
    return r;
}
__device__ __forceinline__ float lo32(uint64_t v) { return __uint_as_float((uint32_t)v); }
__device__ __forceinline__ float hi32(uint64_t v) { return __uint_as_float((uint32_t)(v >> 32)); }

// ---------------- block reduction ----------------
__device__ __forceinline__ float block_sum_256(float v, float* red) {
#pragma unroll
    for (int o = 16; o; o >>= 1) v += __shfl_xor_sync(0xffffffffu, v, o);
    __syncthreads();
    if ((threadIdx.x & 31) == 0) red[threadIdx.x >> 5] = v;
    __syncthreads();
    v = red[threadIdx.x & 7];
#pragma unroll
    for (int o = 4; o; o >>= 1) v += __shfl_xor_sync(0xffffffffu, v, o);
    return v;
}

// ---------------- fused LayerNorm + null-kv/pad fill ----------------
__global__ void ln_fill_kernel(const float* __restrict__ x, const float* __restrict__ gam,
                               const float* __restrict__ bet,
                               const float* __restrict__ null_kv) {
    if (blockIdx.x >= 1024) {
        const int idx = (blockIdx.x - 1024) * 256 + threadIdx.x;
        const int h = idx >> 12;
        const int r = (idx >> 6) & 63;
        const int d = idx & 63;
        if (r < 2) {
            g_k[(h * JPAD + r) * DH + d] = null_kv[((0 * HEADS + h) * 2 + r) * DH + d];
            g_v[(h * JPAD + r) * DH + d] = null_kv[((1 * HEADS + h) * 2 + r) * DH + d];
        } else {
            const int j = 1024 + r;
            g_k[(h * JPAD + j) * DH + d] = 0.0f;
            g_v[(h * JPAD + j) * DH + d] = 0.0f;
        }
        return;
    }
    __shared__ float red[8];
    const int row = blockIdx.x;
    const int tid = threadIdx.x;
    const float v0 = x[row * DIMV + tid];
    const float v1 = x[row * DIMV + tid + 256];
    float s  = v0 + v1;
    float sq = v0 * v0 + v1 * v1;
    s  = block_sum_256(s,  red);
    sq = block_sum_256(sq, red);
    const float mean = s * (1.0f / 512.0f);
    const float var  = sq * (1.0f / 512.0f) - mean * mean;
    const float rstd = rsqrtf(var + 1e-5f);
    g_xn[row * DIMV + tid]       = (v0 - mean) * rstd * gam[tid]       + bet[tid];
    g_xn[row * DIMV + tid + 256] = (v1 - mean) * rstd * gam[tid + 256] + bet[tid + 256];
}

// ---------------- QKV GEMM: 64x64 tiles, f32x2 + reg prefetch ----------------
__global__ void gemm_qkv(const float* __restrict__ B) {
    __shared__ __align__(16) float As[16][64];
    __shared__ __align__(16) float Bs[16][64];
    const float* __restrict__ A = g_xn;
    const int bx = blockIdx.x, by = blockIdx.y, tid = threadIdx.x;
    const int tx = tid & 15, ty = tid >> 4;
    const int ar = tid >> 2, ac = (tid & 3) << 2;
    const int br = tid >> 4, bc = (tid & 15) << 2;
    uint64_t acc2[2][4] = {};

    float4 a4 = *(const float4*)(A + (by * 64 + ar) * 512 + ac);
    float4 b4 = *(const float4*)(B + (size_t)br * 1536 + bx * 64 + bc);

    for (int k0 = 0; k0 < 512; k0 += 16) {
        As[ac + 0][ar] = a4.x; As[ac + 1][ar] = a4.y;
        As[ac + 2][ar] = a4.z; As[ac + 3][ar] = a4.w;
        *(float4*)&Bs[br][bc] = b4;
        __syncthreads();
        if (k0 + 16 < 512) {
            a4 = *(const float4*)(A + (by * 64 + ar) * 512 + k0 + 16 + ac);
            b4 = *(const float4*)(B + (size_t)(k0 + 16 + br) * 1536 + bx * 64 + bc);
        }
#pragma unroll
        for (int kk = 0; kk < 16; kk++) {
            const uint64_t* ap = (const uint64_t*)&As[kk][ty << 2];
            uint64_t ra[2];
            ra[0] = ap[0]; ra[1] = ap[1];
            float4 bq = *(const float4*)&Bs[kk][tx << 2];
            uint64_t rb[4];
            rb[0] = bcast2(bq.x); rb[1] = bcast2(bq.y);
            rb[2] = bcast2(bq.z); rb[3] = bcast2(bq.w);
#pragma unroll
            for (int p = 0; p < 2; p++)
#pragma unroll
                for (int j = 0; j < 4; j++)
                    ffma2(acc2[p][j], ra[p], rb[j]);
        }
        __syncthreads();
    }
#pragma unroll
    for (int p = 0; p < 2; p++) {
#pragma unroll
        for (int j = 0; j < 4; j++) {
            const int col = bx * 64 + (tx << 2) + j;
            const int h = (col >> 6) & 7, d = col & 63, w = col >> 9;
            const int row0 = by * 64 + (ty << 2) + 2 * p;
            const float vlo = lo32(acc2[p][j]);
            const float vhi = hi32(acc2[p][j]);
            if (w == 0) {
                g_q[(h * N_TOK + row0) * DH + d]     = vlo * 0.125f;
                g_q[(h * N_TOK + row0 + 1) * DH + d] = vhi * 0.125f;
            } else if (w == 1) {
                g_k[(h * JPAD + row0 + 2) * DH + d] = vlo;
                g_k[(h * JPAD + row0 + 3) * DH + d] = vhi;
            } else {
                g_v[(h * JPAD + row0 + 2) * DH + d] = vlo;
                g_v[(h * JPAD + row0 + 3) * DH + d] = vhi;
            }
        }
    }
}

// ---------------- out projection GEMM: sums 4 av partials ----------------
__global__ void gemm_proj(const float* __restrict__ B, float* __restrict__ C) {
    __shared__ __align__(16) float As[16][64];
    __shared__ __align__(16) float Bs[16][64];
    const int bx = blockIdx.x, by = blockIdx.y, tid = threadIdx.x;
    const int tx = tid & 15, ty = tid >> 4;
    const int ar = tid >> 2, ac = (tid & 3) << 2;
    const int br = tid >> 4, bc = (tid & 15) << 2;
    uint64_t acc2[2][4] = {};

    const int aoff0 = (by * 64 + ar) * 512 + ac;
    float4 a4  = *(const float4*)(g_o + aoff0);
    float4 a4b = *(const float4*)(g_o2 + aoff0);
    float4 a4c = *(const float4*)(g_o3 + aoff0);
    float4 a4d = *(const float4*)(g_o4 + aoff0);
    a4.x = (a4.x + a4b.x) + (a4c.x + a4d.x);
    a4.y = (a4.y + a4b.y) + (a4c.y + a4d.y);
    a4.z = (a4.z + a4b.z) + (a4c.z + a4d.z);
    a4.w = (a4.w + a4b.w) + (a4c.w + a4d.w);
    float4 b4 = *(const float4*)(B + (size_t)br * 512 + bx * 64 + bc);

    for (int k0 = 0; k0 < 512; k0 += 16) {
        As[ac + 0][ar] = a4.x; As[ac + 1][ar] = a4.y;
        As[ac + 2][ar] = a4.z; As[ac + 3][ar] = a4.w;
        *(float4*)&Bs[br][bc] = b4;
        __syncthreads();
        if (k0 + 16 < 512) {
            const int aoff = (by * 64 + ar) * 512 + k0 + 16 + ac;
            a4  = *(const float4*)(g_o + aoff);
            a4b = *(const float4*)(g_o2 + aoff);
            a4c = *(const float4*)(g_o3 + aoff);
            a4d = *(const float4*)(g_o4 + aoff);
            a4.x = (a4.x + a4b.x) + (a4c.x + a4d.x);
            a4.y = (a4.y + a4b.y) + (a4c.y + a4d.y);
            a4.z = (a4.z + a4b.z) + (a4c.z + a4d.z);
            a4.w = (a4.w + a4b.w) + (a4c.w + a4d.w);
            b4 = *(const float4*)(B + (size_t)(k0 + 16 + br) * 512 + bx * 64 + bc);
        }
#pragma unroll
        for (int kk = 0; kk < 16; kk++) {
            const uint64_t* ap = (const uint64_t*)&As[kk][ty << 2];
            uint64_t ra[2];
            ra[0] = ap[0]; ra[1] = ap[1];
            float4 bq = *(const float4*)&Bs[kk][tx << 2];
            uint64_t rb[4];
            rb[0] = bcast2(bq.x); rb[1] = bcast2(bq.y);
            rb[2] = bcast2(bq.z); rb[3] = bcast2(bq.w);
#pragma unroll
            for (int p = 0; p < 2; p++)
#pragma unroll
                for (int j = 0; j < 4; j++)
                    ffma2(acc2[p][j], ra[p], rb[j]);
        }
        __syncthreads();
    }
#pragma unroll
    for (int p = 0; p < 2; p++) {
        const int row0 = by * 64 + (ty << 2) + 2 * p;
        const int colb = bx * 64 + (tx << 2);
        C[row0 * 512 + colb + 0] = lo32(acc2[p][0]);
        C[row0 * 512 + colb + 1] = lo32(acc2[p][1]);
        C[row0 * 512 + colb + 2] = lo32(acc2[p][2]);
        C[row0 * 512 + colb + 3] = lo32(acc2[p][3]);
        C[(row0 + 1) * 512 + colb + 0] = hi32(acc2[p][0]);
        C[(row0 + 1) * 512 + colb + 1] = hi32(acc2[p][1]);
        C[(row0 + 1) * 512 + colb + 2] = hi32(acc2[p][2]);
        C[(row0 + 1) * 512 + colb + 3] = hi32(acc2[p][3]);
    }
}

// ---------------- sim = q . k^T: 128(i) x 64(j) tiles, f32x2, occ 3 -------------------
__global__ void __launch_bounds__(256, 3) sim_kernel() {
    const int f = blockIdx.x;
    const int h = blockIdx.y;
    int it2 = __float2int_rd(sqrtf((float)(f + 1))) - 1;
    while ((it2 + 1) * (it2 + 3) <= f) it2++;
    while (it2 * (it2 + 2) > f) it2--;
    const int jt = f - it2 * (it2 + 2);

    __shared__ __align__(16) float Qs[32][132];
    __shared__ __align__(16) float Ks[32][68];
    const int tid = threadIdx.x;
    const int tx = tid & 15, ty = tid >> 4;
    uint64_t acc2[4][4] = {};

#pragma unroll
    for (int dc = 0; dc < 64; dc += 32) {
        {
            const int row = tid >> 1;
            const int base = ((h << 10) + it2 * 128 + row) * DH + dc + ((tid & 1) << 4);
#pragma unroll
            for (int t = 0; t < 4; t++) {
                float4 q4 = *(const float4*)&g_q[base + t * 4];
                const int off = ((tid & 1) << 4) + t * 4;
                Qs[off + 0][row] = q4.x; Qs[off + 1][row] = q4.y;
                Qs[off + 2][row] = q4.z; Qs[off + 3][row] = q4.w;
            }
        }
        {
            const int row = tid >> 2;
            const int base = (h * JPAD + jt * 64 + row) * DH + dc + ((tid & 3) << 3);
#pragma unroll
            for (int t = 0; t < 2; t++) {
                float4 k4 = *(const float4*)&g_k[base + t * 4];
                const int off = ((tid & 3) << 3) + t * 4;
                Ks[off + 0][row] = k4.x; Ks[off + 1][row] = k4.y;
                Ks[off + 2][row] = k4.z; Ks[off + 3][row] = k4.w;
            }
        }
        __syncthreads();
#pragma unroll 8
        for (int d = 0; d < 32; d++) {
            const uint64_t* ap = (const uint64_t*)&Qs[d][ty << 3];
            uint64_t ra[4];
            ra[0] = ap[0]; ra[1] = ap[1]; ra[2] = ap[2]; ra[3] = ap[3];
            float4 kq = *(const float4*)&Ks[d][tx << 2];
            uint64_t rb[4];
            rb[0] = bcast2(kq.x); rb[1] = bcast2(kq.y);
            rb[2] = bcast2(kq.z); rb[3] = bcast2(kq.w);
#pragma unroll
            for (int p = 0; p < 4; p++)
#pragma unroll
                for (int j = 0; j < 4; j++)
                    ffma2(acc2[p][j], ra[p], rb[j]);
        }
        __syncthreads();
    }
#pragma unroll
    for (int p = 0; p < 4; p++) {
        const int i0 = it2 * 128 + (ty << 3) + 2 * p;
        float* sr0 = g_s + (size_t)(h * N_TOK + i0) * JPAD + jt * 64 + (tx << 2);
        float* sr1 = sr0 + JPAD;
        *(float4*)sr0 = make_float4(lo32(acc2[p][0]), lo32(acc2[p][1]),
                                    lo32(acc2[p][2]), lo32(acc2[p][3]));
        *(float4*)sr1 = make_float4(hi32(acc2[p][0]), hi32(acc2[p][1]),
                                    hi32(acc2[p][2]), hi32(acc2[p][3]));
    }
}

// ---------------- coordinate descent: Aitken-accelerated fixed point ------------------
template<int MAXU>
__device__ __forceinline__ float cd_F(const float* E1, int nchunk, int jmax,
                                      float m, float a, int lane) {
    const float w = __expf((a + m) * INV_EPS);
    float ls0 = 0.0f, ls1 = 0.0f;
#pragma unroll
    for (int u = 0; u < MAXU; u++) {
        if (u < nchunk) {
            const float e = E1[u];
            const float c = fminf(e, w * (e * e));
            if (u & 1) ls1 += c; else ls0 += c;
        }
    }
    float ls = ls0 + ls1;
#pragma unroll
    for (int o = 16; o; o >>= 1) ls += __shfl_xor_sync(0xffffffffu, ls, o);
    return EPSF * LOGK - m - EPSF * __logf(ls);
}

template<int MAXU>
__device__ __forceinline__ void cd_row(float* __restrict__ srow, int lane, int jmax,
                                       int nchunk, int chunks) {
    float E1[MAXU];
    float tm = -3.4e38f;
#pragma unroll
    for (int u = 0; u < MAXU; u++) {
        E1[u] = -3.4e38f;
        if (u < nchunk) {
            const int j = lane + u * 32;
            if (j < jmax) { E1[u] = srow[j]; tm = fmaxf(tm, E1[u]); }
        }
    }
#pragma unroll
    for (int o = 16; o; o >>= 1) tm = fmaxf(tm, __shfl_xor_sync(0xffffffffu, tm, o));
    const float m = tm;
#pragma unroll
    for (int u = 0; u < MAXU; u++)
        if (u < nchunk)
            E1[u] = (E1[u] > -3.0e38f) ? __expf((E1[u] - m) * INV_EPS) : 0.0f;

    float a = EPSF * (LOGK - __logf((float)jmax));   // iteration 1 closed form

    // Aitken-accelerated fixed-point loop: 2 F-evals + 1 extrapolation per cycle.
    for (int it = 1; it < CD_ITERS; ) {
        const float f1 = cd_F<MAXU>(E1, nchunk, jmax, m, a, lane);
        it++;
        if (fabsf(f1 - a) < 5e-7f) { a = f1; break; }
        const float f2 = cd_F<MAXU>(E1, nchunk, jmax, m, f1, lane);
        it++;
        if (fabsf(f2 - f1) < 5e-7f) { a = f2; break; }
        const float d2 = (f2 - f1) - (f1 - a);
        float aa = f2;
        if (fabsf(d2) > 1e-12f) {
            const float cand = a - (f1 - a) * (f1 - a) / d2;
            if (cand == cand) aa = cand;            // NaN guard
        }
        a = aa;
    }

    const float w = __expf((a + m) * INV_EPS);
#pragma unroll
    for (int u = 0; u < MAXU + 3; u++) {
        if (u < chunks) {
            const int j = lane + u * 32;
            float val = 0.0f;
            if (u < MAXU && u < nchunk) {
                const float eu = w * E1[u];
                val = fminf(eu, eu * eu);
            }
            srow[j] = val;
        }
    }
}

__global__ void cd_kernel() {
    const int wg   = (blockIdx.x * blockDim.x + threadIdx.x) >> 5;
    const int lane = threadIdx.x & 31;
    const int i = wg >> 3, h = wg & 7;
    const int jmax = i + 3;
    const int nchunk = (jmax + 31) >> 5;
    const int chunks = ((i >> 6) + 2) << 1;
    float* srow = g_s + (size_t)(h * N_TOK + i) * JPAD;
    if (i < 254)      cd_row<8 >(srow, lane, jmax, nchunk, chunks);
    else if (i < 510) cd_row<16>(srow, lane, jmax, nchunk, chunks);
    else if (i < 766) cd_row<24>(srow, lane, jmax, nchunk, chunks);
    else              cd_row<33>(srow, lane, jmax, nchunk, chunks);
}

// ---------------- out = attn . v : split-K 4 over 32-j chunks, f32x2 ------------------
__global__ void av_kernel() {
    const int it = blockIdx.x;
    const int h  = blockIdx.y;
    const int sp = blockIdx.z;                 // 0..3
    const int C = 2 * (it + 2);                // total 32-j chunks
    const int c0 = (C * sp) >> 2;
    const int c1 = (C * (sp + 1)) >> 2;

    __shared__ __align__(16) float Ps[32][66];
    __shared__ __align__(16) float Vs[32][68];
    const int tid = threadIdx.x;
    const int tx = tid & 15, ty = tid >> 4;
    const int pi = tid >> 2, pj = (tid & 3) << 3;
    const int vj = tid >> 3, vd = (tid & 7) << 3;
    uint64_t acc2[2][4] = {};

    for (int jc = c0; jc < c1; jc++) {
        const float* pg = g_s + (size_t)(h * N_TOK + it * 64 + pi) * JPAD + jc * 32 + pj;
        float4 p0 = *(const float4*)pg;
        float4 p1 = *(const float4*)(pg + 4);
        Ps[pj + 0][pi] = p0.x; Ps[pj + 1][pi] = p0.y;
        Ps[pj + 2][pi] = p0.z; Ps[pj + 3][pi] = p0.w;
        Ps[pj + 4][pi] = p1.x; Ps[pj + 5][pi] = p1.y;
        Ps[pj + 6][pi] = p1.z; Ps[pj + 7][pi] = p1.w;
        const float* vg = g_v + (h * JPAD + jc * 32 + vj) * DH + vd;
        *(float4*)&Vs[vj][vd]     = *(const float4*)vg;
        *(float4*)&Vs[vj][vd + 4] = *(const float4*)(vg + 4);
        __syncthreads();
#pragma unroll 8
        for (int j = 0; j < 32; j++) {
            const uint64_t* ap = (const uint64_t*)&Ps[j][ty << 2];
            uint64_t ra[2];
            ra[0] = ap[0]; ra[1] = ap[1];
            float4 vq = *(const float4*)&Vs[j][tx << 2];
            uint64_t rb[4];
            rb[0] = bcast2(vq.x); rb[1] = bcast2(vq.y);
            rb[2] = bcast2(vq.z); rb[3] = bcast2(vq.w);
#pragma unroll
            for (int p = 0; p < 2; p++)
#pragma unroll
                for (int jj = 0; jj < 4; jj++)
                    ffma2(acc2[p][jj], ra[p], rb[jj]);
        }
        __syncthreads();
    }
    float* outp = (sp == 0) ? g_o : (sp == 1) ? g_o2 : (sp == 2) ? g_o3 : g_o4;
#pragma unroll
    for (int p = 0; p < 2; p++) {
        const int row0 = it * 64 + (ty << 2) + 2 * p;
        float* o0 = outp + row0 * DIMV + h * DH + (tx << 2);
        float* o1 = o0 + DIMV;
        *(float4*)o0 = make_float4(lo32(acc2[p][0]), lo32(acc2[p][1]),
                                   lo32(acc2[p][2]), lo32(acc2[p][3]));
        *(float4*)o1 = make_float4(hi32(acc2[p][0]), hi32(acc2[p][1]),
                                   hi32(acc2[p][2]), hi32(acc2[p][3]));
    }
}

// ---------------- launch ----------------
extern "C" void kernel_launch(void* const* d_in, const int* in_sizes, int n_in,
                              void* d_out, int out_size) {
    const float* x       = (const float*)d_in[0];
    const float* w_qkv   = (const float*)d_in[1];
    const float* w_out   = (const float*)d_in[2];
    const float* null_kv = (const float*)d_in[3];
    const float* ln_g    = (const float*)d_in[4];
    const float* ln_b    = (const float*)d_in[5];
    float* out = (float*)d_out;

    ln_fill_kernel<<<1152, 256>>>(x, ln_g, ln_b, null_kv);
    gemm_qkv   <<<dim3(24, 16), 256>>>(w_qkv);
    sim_kernel <<<dim3(80, HEADS), 256>>>();
    cd_kernel  <<<2048, 128>>>();
    av_kernel  <<<dim3(16, HEADS, 4), 256>>>();
    gemm_proj  <<<dim3(8, 16), 256>>>(w_out, out);
}